// round 7
// baseline (speedup 1.0000x reference)
#include <cuda_runtime.h>

// Chunked SSM:  T=64 chunk, M=64 chunks, n=64 state, CH=128 channels, B=16.
// y[b,c,m*64+jj] = Toeplitz(k, u_chunk) + Ghat[jj]·x[b,m] + D[c]*u
// Ghat[jj] = CH[hi]·A^l, jj+1 = 8*hi + l;  CH built by doubling tree (depth 3).
// GEMM: per 2-channel block  Y(128x64) = [Ktoep | Ghat](128x128) @ [U ; X](128x64)

#define MPAD 68
#define GA 132
#define GZ 68

__device__ float g_AP[9][4096];      // A_bar^p, p=1..8
__device__ float g_A16[4096], g_A32[4096], g_A64[4096];
__device__ float g_CH[8][8192];      // CH[h] = C * A8^h (h=1..7)
__device__ float g_W[64][64];        // W[j] = A_bar^j B_bar
__device__ float g_ktab[64][128];    // k[j][c]
__device__ float g_G[64][8192];      // Ghat[jj][c*64+s]
__device__ float g_Z[128][1024];     // rows 0..63 u-chunks, 64..127 states

// ---------------- packed f32x2 helpers ----------------
#define PACK2(d, x) asm("mov.b64 %0, {%1, %1};" : "=l"(d) : "r"(__float_as_uint(x)))
#define FMA2(d, a, b) asm("fma.rn.f32x2 %0, %1, %2, %0;" : "+l"(d) : "l"(a), "l"(b))

__device__ __forceinline__ float f32x2_get(unsigned long long v, int hi) {
    return hi ? __uint_as_float((unsigned)(v >> 32)) : __uint_as_float((unsigned)v);
}

// ---------------- register-blocked 64x64 matmul core ----------------
__device__ __forceinline__ void mm64R(const float* __restrict__ xT,
                                      const float* __restrict__ ys,
                                      float* __restrict__ O, int tid) {
    int tr = tid & 15, tc = tid >> 4;
    float a00=0,a01=0,a02=0,a03=0, a10=0,a11=0,a12=0,a13=0;
    float a20=0,a21=0,a22=0,a23=0, a30=0,a31=0,a32=0,a33=0;
    #pragma unroll 4
    for (int s = 0; s < 64; s++) {
        float4 xv = *(const float4*)(xT + s * MPAD + tr * 4);
        float4 yv = *(const float4*)(ys + s * MPAD + tc * 4);
        a00 += xv.x*yv.x; a01 += xv.x*yv.y; a02 += xv.x*yv.z; a03 += xv.x*yv.w;
        a10 += xv.y*yv.x; a11 += xv.y*yv.y; a12 += xv.y*yv.z; a13 += xv.y*yv.w;
        a20 += xv.z*yv.x; a21 += xv.z*yv.y; a22 += xv.z*yv.z; a23 += xv.z*yv.w;
        a30 += xv.w*yv.x; a31 += xv.w*yv.y; a32 += xv.w*yv.z; a33 += xv.w*yv.w;
    }
    float4 o0 = {a00,a01,a02,a03}; *(float4*)(O + (tr*4+0)*64 + tc*4) = o0;
    float4 o1 = {a10,a11,a12,a13}; *(float4*)(O + (tr*4+1)*64 + tc*4) = o1;
    float4 o2 = {a20,a21,a22,a23}; *(float4*)(O + (tr*4+2)*64 + tc*4) = o2;
    float4 o3 = {a30,a31,a32,a33}; *(float4*)(O + (tr*4+3)*64 + tc*4) = o3;
}

__device__ __forceinline__ void loadT(const float* __restrict__ G, float* xT, int tid) {
    for (int idx = tid; idx < 4096; idx += 256) {
        int i = idx >> 6, s = idx & 63;
        xT[s * MPAD + i] = G[idx];
    }
}
__device__ __forceinline__ void loadN(const float* __restrict__ G, float* ys, int tid) {
    for (int idx = tid; idx < 4096; idx += 256)
        ys[(idx >> 6) * MPAD + (idx & 63)] = G[idx];
}
// xT[s][i] = M[i][s] for a 64-row slice of a [rows x 64] matrix
__device__ __forceinline__ void loadTrows(const float* __restrict__ G, int row0,
                                          float* xT, int tid) {
    for (int idx = tid; idx < 4096; idx += 256) {
        int i = idx >> 6, s = idx & 63;
        xT[s * MPAD + i] = G[(row0 + i) * 64 + s];
    }
}

// ---------------------------------------------------------------------------
// K1: discretization. Column-parallel forward substitution (E lower-tri),
// then A2 = A_bar^2 (register-blocked). Stores AP[1], W[0] (=B_bar).
// ---------------------------------------------------------------------------
__global__ __launch_bounds__(256) void k_disc(const float* __restrict__ A,
                                              const float* __restrict__ B,
                                              const float* __restrict__ dtp) {
    extern __shared__ float sm[];
    float* Ao = sm;                 // [64][65]
    float* Xs = sm + 64 * 65;       // [64][MPAD]  cols 0..63 A_bar, col 64 B_bar
    float* xT = Xs + 64 * MPAD;     // [64][MPAD]  A_bar transposed
    __shared__ float rdiag[64];
    int tid = threadIdx.x;
    float dt = dtp[0], hd = 0.5f * dt;
    for (int idx = tid; idx < 4096; idx += 256)
        Ao[(idx >> 6) * 65 + (idx & 63)] = A[idx];
    __syncthreads();
    if (tid < 64) rdiag[tid] = 1.f / (1.f - hd * Ao[tid * 65 + tid]);
    __syncthreads();
    if (tid < 65) {
        int c = tid;
        for (int i = 0; i < 64; i++) {
            float acc0, acc1 = 0.f;
            if (c < 64) acc0 = ((i == c) ? 1.f : 0.f) + hd * Ao[i * 65 + c];
            else        acc0 = dt * B[i];
            int j = 0;
            for (; j + 1 < i; j += 2) {
                acc0 += hd * Ao[i * 65 + j]     * Xs[j * MPAD + c];
                acc1 += hd * Ao[i * 65 + j + 1] * Xs[(j + 1) * MPAD + c];
            }
            if (j < i) acc0 += hd * Ao[i * 65 + j] * Xs[j * MPAD + c];
            Xs[i * MPAD + c] = (acc0 + acc1) * rdiag[i];
        }
    }
    __syncthreads();
    for (int idx = tid; idx < 4096; idx += 256) {
        int i = idx >> 6, s = idx & 63;
        float v = Xs[i * MPAD + s];
        g_AP[1][idx] = v;
        xT[s * MPAD + i] = v;
    }
    if (tid < 64) g_W[0][tid] = Xs[tid * MPAD + 64];
    __syncthreads();
    mm64R(xT, Xs, g_AP[2], tid);
}

// ---------------------------------------------------------------------------
// K2: power/CH tree stages (all mm64R blocks + small vector work).
//  stage 0 (2 blk):  A3=A1*A2, A4=A2*A2
//  stage 1 (4 blk):  A8=A4*A4, A5..A7 = A4*A{1..3}
//  stage 2 (4 blk):  A16=A8^2 | CH1=C*A8 (2 blk) | w8 chain -> g_W[8q]
//  stage 3 (5 blk):  A32=A16^2 | CH2=C*A16 (2) | CH3=CH1*A16 (2)
//  stage 4 (13 blk): A64=A32^2 | CH4..7 = {C,CH1,CH2,CH3}*A32 (8) |
//                    W expansion W[8q+r]=A^r*w8[q] (4 blk)
// ---------------------------------------------------------------------------
__global__ __launch_bounds__(256) void k_mul2(int stage, const float* __restrict__ C) {
    __shared__ float s1[64 * MPAD];
    __shared__ float s2[64 * MPAD];
    __shared__ float aux[704];
    int tid = threadIdx.x, bid = blockIdx.x;

    if (stage == 0) {
        loadT(bid ? g_AP[1] : g_AP[2], s1, tid);
        loadN(g_AP[2], s2, tid);
        __syncthreads();
        mm64R(s1, s2, bid ? g_AP[3] : g_AP[4], tid);
        return;
    }
    if (stage == 1) {
        loadT(g_AP[4], s1, tid);
        loadN(bid ? g_AP[bid] : g_AP[4], s2, tid);
        __syncthreads();
        mm64R(s1, s2, bid ? g_AP[4 + bid] : g_AP[8], tid);
        return;
    }
    if (stage == 2) {
        if (bid < 3) {
            if (bid == 0) loadT(g_AP[8], s1, tid);
            else          loadTrows(C, (bid - 1) * 64, s1, tid);
            loadN(g_AP[8], s2, tid);
            __syncthreads();
            mm64R(s1, s2, bid == 0 ? g_A16 : g_CH[1] + (bid - 1) * 4096, tid);
            return;
        }
        // w8 chain: w8[q] = A8^q B_bar, stored to g_W[8q]
        loadN(g_AP[8], s2, tid);                     // s2[i][s] = A8[i][s]
        if (tid < 64) aux[tid] = g_W[0][tid];
        __syncthreads();
        int i = tid & 63, q4 = tid >> 6;
        for (int q = 1; q < 8; q++) {
            float acc = 0.f;
            #pragma unroll
            for (int s = q4 * 16; s < q4 * 16 + 16; s++)
                acc += s2[i * MPAD + s] * aux[s];
            aux[64 + q4 * 64 + i] = acc;
            __syncthreads();
            if (q4 == 0) {
                float v = aux[64 + i] + aux[128 + i] + aux[192 + i] + aux[256 + i];
                aux[i] = v;
                g_W[8 * q][i] = v;
            }
            __syncthreads();
        }
        return;
    }
    if (stage == 3) {
        if (bid == 0)      { loadT(g_A16, s1, tid); }
        else if (bid <= 2) { loadTrows(C, (bid - 1) * 64, s1, tid); }
        else               { loadTrows(g_CH[1], (bid - 3) * 64, s1, tid); }
        loadN(g_A16, s2, tid);
        __syncthreads();
        float* O = (bid == 0) ? g_A32
                 : (bid <= 2) ? g_CH[2] + (bid - 1) * 4096
                              : g_CH[3] + (bid - 3) * 4096;
        mm64R(s1, s2, O, tid);
        return;
    }
    // stage 4
    if (bid == 0) {
        loadT(g_A32, s1, tid); loadN(g_A32, s2, tid);
        __syncthreads();
        mm64R(s1, s2, g_A64, tid);
        return;
    }
    if (bid <= 8) {
        int p = bid - 1, which = p >> 1, half = p & 1;
        const float* srcs[4] = { C, g_CH[1], g_CH[2], g_CH[3] };
        loadTrows(srcs[which], half * 64, s1, tid);
        loadN(g_A32, s2, tid);
        __syncthreads();
        mm64R(s1, s2, g_CH[4 + which] + half * 4096, tid);
        return;
    }
    // W expansion: block p handles r0 = 2p+1, r1 = 2p+2 (r1<8)
    {
        int p = bid - 9;
        int r0 = 2 * p + 1, r1 = 2 * p + 2;
        loadN(g_AP[r0], s1, tid);
        if (r1 < 8) loadN(g_AP[r1], s2, tid);
        for (int idx = tid; idx < 512; idx += 256)
            aux[idx] = g_W[8 * (idx >> 6)][idx & 63];     // aux[q*64+s] = w8[q][s]
        __syncthreads();
        for (int idx = tid; idx < 512; idx += 256) {
            int q = idx >> 6, i = idx & 63;
            float a0 = 0.f, a1 = 0.f;
            #pragma unroll 8
            for (int s = 0; s < 64; s += 2) {
                a0 += s1[i * MPAD + s]     * aux[q * 64 + s];
                a1 += s1[i * MPAD + s + 1] * aux[q * 64 + s + 1];
            }
            g_W[8 * q + r0][i] = a0 + a1;
            if (r1 < 8) {
                float b0 = 0.f, b1 = 0.f;
                #pragma unroll 8
                for (int s = 0; s < 64; s += 2) {
                    b0 += s2[i * MPAD + s]     * aux[q * 64 + s];
                    b1 += s2[i * MPAD + s + 1] * aux[q * 64 + s + 1];
                }
                g_W[8 * q + r1][i] = b0 + b1;
            }
        }
    }
}

// ---------------------------------------------------------------------------
// K3 (merged): blocks 0..127 Ghat; 128..135 ktab; 136..151 per-batch prep.
// ktab uses the FULL W table: ktab[j][c] = C[c]·W[j]  (C directly — W[j]
// already carries the whole A^j power; multiplying by CH[hi] would double it).
// ---------------------------------------------------------------------------
__global__ __launch_bounds__(256) void k_pg(const float* __restrict__ C,
                                            const float* __restrict__ u) {
    extern __shared__ float sm[];
    int tid = threadIdx.x, bid = blockIdx.x;

    if (bid < 128) {
        float* xT = sm;                 // [64][MPAD]
        float* ys = sm + 64 * MPAD;     // [64][MPAD]
        int jj = bid >> 1, ch0 = (bid & 1) << 6;
        int hi = jj >> 3, l = (jj & 7) + 1;
        const float* __restrict__ CHp = hi ? g_CH[hi] : C;
        loadTrows(CHp, ch0, xT, tid);
        loadN(g_AP[l], ys, tid);
        __syncthreads();
        mm64R(xT, ys, g_G[jj] + ch0 * 64, tid);
        return;
    }
    if (bid < 136) {
        float* Cs = sm;                 // [128][65]
        float* ws = sm + 128 * 65;      // [8][64]   ws[lo][s] = W[8hi+lo][s]
        int hi = bid - 128;
        for (int idx = tid; idx < 8192; idx += 256)
            Cs[(idx >> 6) * 65 + (idx & 63)] = C[idx];
        for (int idx = tid; idx < 512; idx += 256)
            ws[idx] = g_W[8 * hi + (idx >> 6)][idx & 63];
        __syncthreads();
        int c = tid >> 1, lo0 = (tid & 1) * 4;
        float a0 = 0, a1 = 0, a2 = 0, a3 = 0;
        #pragma unroll 4
        for (int s = 0; s < 64; s++) {
            float cv = Cs[c * 65 + s];
            a0 += cv * ws[(lo0 + 0) * 64 + s];
            a1 += cv * ws[(lo0 + 1) * 64 + s];
            a2 += cv * ws[(lo0 + 2) * 64 + s];
            a3 += cv * ws[(lo0 + 3) * 64 + s];
        }
        g_ktab[hi * 8 + lo0 + 0][c] = a0;
        g_ktab[hi * 8 + lo0 + 1][c] = a1;
        g_ktab[hi * 8 + lo0 + 2][c] = a2;
        g_ktab[hi * 8 + lo0 + 3][c] = a3;
        return;
    }
    // prep: b = bid - 136
    {
        float* us  = sm;                  // [64][66]
        float* Fs  = sm + 64 * 66;        // [64][65]  Fs[i][s] = W[63-i][s]
        float* Sm  = Fs + 64 * 65;        // [64][65]
        float* ATs = Sm + 64 * 65;        // [64][65]  A_bar^64
        float* xv  = ATs + 64 * 65;       // [64]
        float* part = xv + 64;            // [4][64]
        int b = bid - 136;
        for (int idx = tid; idx < 4096; idx += 256) {
            int m = idx >> 6, j = idx & 63;
            us[m * 66 + j] = u[b * 4096 + idx];
        }
        for (int idx = tid; idx < 4096; idx += 256) {
            int i = idx >> 6, s = idx & 63;
            Fs[i * 65 + s]  = g_W[63 - i][s];
            ATs[i * 65 + s] = g_A64[idx];
        }
        __syncthreads();
        for (int idx = tid; idx < 4096; idx += 256) {
            int m = idx >> 6, s = idx & 63;
            float a0 = 0, a1 = 0;
            #pragma unroll 8
            for (int i = 0; i < 64; i += 2) {
                a0 += Fs[i * 65 + s]       * us[m * 66 + i];
                a1 += Fs[(i + 1) * 65 + s] * us[m * 66 + i + 1];
            }
            Sm[m * 65 + s] = a0 + a1;
        }
        for (int idx = tid; idx < 4096; idx += 256) {
            int j = idx >> 6, m = idx & 63;
            g_Z[j][b * 64 + m] = us[m * 66 + j];
        }
        if (tid < 64) xv[tid] = 0.f;
        __syncthreads();
        int s = tid & 63, q = tid >> 6;
        for (int m = 0; m < 64; m++) {
            if (q == 0) g_Z[64 + s][b * 64 + m] = xv[s];
            float acc = 0.f;
            #pragma unroll
            for (int s2 = q * 16; s2 < q * 16 + 16; s2++)
                acc += ATs[s * 65 + s2] * xv[s2];
            part[q * 64 + s] = acc;
            __syncthreads();
            if (q == 0)
                xv[s] = part[s] + part[64 + s] + part[128 + s] + part[192 + s]
                      + Sm[m * 65 + s];
            __syncthreads();
        }
    }
}

// ---------------------------------------------------------------------------
// K4: GEMM. Block = (2 channels, 64 cols): Y(128x64). A-tile As[k][m],
// m = cc*64+jj. 128 threads, 8x8 micro-tile via FFMA2.
// ---------------------------------------------------------------------------
__global__ __launch_bounds__(128) void k_gemm(const float* __restrict__ D,
                                              float* __restrict__ out) {
    extern __shared__ float sm[];
    float* As = sm;                   // [128][GA]
    float* Zs = sm + 128 * GA;        // [128][GZ]
    float* kt = Zs + 128 * GZ;        // [128]  kt[cc*64+j]
    int tid = threadIdx.x;
    int n0 = blockIdx.x * 64;
    int c0 = blockIdx.y * 2;

    if (tid < 128) kt[tid] = g_ktab[tid & 63][c0 + (tid >> 6)];
    for (int idx = tid; idx < 8192; idx += 128) {
        int k = idx >> 6, n = idx & 63;
        Zs[k * GZ + n] = g_Z[k][n0 + n];
    }
    for (int idx = tid; idx < 8192; idx += 128) {
        int s = idx & 63, jj = (idx >> 6) & 63, cc = idx >> 12;
        As[(64 + s) * GA + cc * 64 + jj] = g_G[jj][(c0 + cc) * 64 + s];
    }
    __syncthreads();
    for (int idx = tid; idx < 8192; idx += 128) {
        int jj = idx & 63, k = (idx >> 6) & 63, cc = idx >> 12;
        As[k * GA + cc * 64 + jj] = (k <= jj) ? kt[cc * 64 + (jj - k)] : 0.f;
    }
    __syncthreads();

    int tr = tid & 15, tc = tid >> 4;          // tr: row group, tc: 0..7 col group
    const float* Ab = As + tr * 4;
    const float* Zb = Zs + tc * 8;

    unsigned long long acc[8][4];
    #pragma unroll
    for (int i = 0; i < 8; i++)
        #pragma unroll
        for (int j = 0; j < 4; j++) acc[i][j] = 0ull;

    #pragma unroll 2
    for (int k = 0; k < 128; k++) {
        float4 a0 = *(const float4*)(Ab + k * GA);          // jj=tr*4..+3   (ch c0)
        float4 a1 = *(const float4*)(Ab + k * GA + 64);     // same jj       (ch c0+1)
        ulonglong2 zl = *(const ulonglong2*)(Zb + k * GZ);
        ulonglong2 zh = *(const ulonglong2*)(Zb + k * GZ + 4);
        unsigned long long zp[4] = { zl.x, zl.y, zh.x, zh.y };
        unsigned long long ap[8];
        PACK2(ap[0], a0.x); PACK2(ap[1], a0.y); PACK2(ap[2], a0.z); PACK2(ap[3], a0.w);
        PACK2(ap[4], a1.x); PACK2(ap[5], a1.y); PACK2(ap[6], a1.z); PACK2(ap[7], a1.w);
        #pragma unroll
        for (int ri = 0; ri < 8; ri++)
            #pragma unroll
            for (int cj = 0; cj < 4; cj++)
                FMA2(acc[ri][cj], ap[ri], zp[cj]);
    }

    float Dv0 = D[c0], Dv1 = D[c0 + 1];
    int jb = tr * 4;
    #pragma unroll
    for (int j = 0; j < 8; j++) {
        int n = tc * 8 + j, gn = n0 + n, b = gn >> 6, mm = gn & 63;
        int cj = j >> 1, lh = j & 1;
        float u0 = Zs[(jb + 0) * GZ + n];
        float u1 = Zs[(jb + 1) * GZ + n];
        float u2 = Zs[(jb + 2) * GZ + n];
        float u3 = Zs[(jb + 3) * GZ + n];
        float4 o0 = { f32x2_get(acc[0][cj], lh) + Dv0 * u0,
                      f32x2_get(acc[1][cj], lh) + Dv0 * u1,
                      f32x2_get(acc[2][cj], lh) + Dv0 * u2,
                      f32x2_get(acc[3][cj], lh) + Dv0 * u3 };
        *(float4*)&out[(b * 128 + c0) * 4096 + mm * 64 + jb] = o0;
        float4 o1 = { f32x2_get(acc[4][cj], lh) + Dv1 * u0,
                      f32x2_get(acc[5][cj], lh) + Dv1 * u1,
                      f32x2_get(acc[6][cj], lh) + Dv1 * u2,
                      f32x2_get(acc[7][cj], lh) + Dv1 * u3 };
        *(float4*)&out[(b * 128 + c0 + 1) * 4096 + mm * 64 + jb] = o1;
    }
}

// ---------------------------------------------------------------------------
extern "C" void kernel_launch(void* const* d_in, const int* in_sizes, int n_in,
                              void* d_out, int out_size) {
    const float *u = 0, *A = 0, *B = 0, *C = 0, *D = 0, *dt = 0;
    for (int i = 0; i < n_in; i++) {
        const float* p = (const float*)d_in[i];
        switch (in_sizes[i]) {
            case 65536: u = p;  break;
            case 4096:  A = p;  break;
            case 64:    B = p;  break;
            case 8192:  C = p;  break;
            case 128:   D = p;  break;
            case 1:     dt = p; break;
        }
    }
    const int disc_smem = (64 * 65 + 2 * 64 * MPAD) * sizeof(float);            // 51456
    const int pg_smem   = (64 * 66 + 3 * 64 * 65 + 64 + 256) * sizeof(float);   // 68096
    const int gemm_smem = (128 * GA + 128 * GZ + 128) * sizeof(float);          // 102912
    cudaFuncSetAttribute(k_disc, cudaFuncAttributeMaxDynamicSharedMemorySize, disc_smem);
    cudaFuncSetAttribute(k_pg,   cudaFuncAttributeMaxDynamicSharedMemorySize, pg_smem);
    cudaFuncSetAttribute(k_gemm, cudaFuncAttributeMaxDynamicSharedMemorySize, gemm_smem);

    k_disc<<<1, 256, disc_smem>>>(A, B, dt);
    k_mul2<<<2, 256>>>(0, C);
    k_mul2<<<4, 256>>>(1, C);
    k_mul2<<<4, 256>>>(2, C);
    k_mul2<<<5, 256>>>(3, C);
    k_mul2<<<13, 256>>>(4, C);
    k_pg<<<152, 256, pg_smem>>>(C, u);
    k_gemm<<<dim3(16, 64), 128, gemm_smem>>>(D, (float*)d_out);
}

// round 8
// speedup vs baseline: 1.0137x; 1.0137x over previous
#include <cuda_runtime.h>

// Fully fused chunked-SSM kernel. One launch, grid-wide software barriers.
//   T=64 chunk, M=64 chunks, n=64 state, CH=128 channels, B=16.
// Phases:
//   P0: bilinear discretization (A_bar, B_bar), A2            [block 0]
//   P1: A4, A8, w8[q]=A8^q B_bar                              [block 0, serial]
//   P2: A16=A8^2 | CH1=C*A8 | A3,A7 | A5 | A6                 [blocks 0..5]
//   P3: A32 | CH2=C*A16 | CH3=CH1*A16 | W[8q+r]=A^r w8[q]     [blocks 0..8]
//   P4: A64 | CH4..7={C,CH1..3}*A32 | ktab[j][c]=C[c]·W[j]    [blocks 0..16]
//   P5: Ghat[jj]=CH[hi]*A^l (128 blk) | per-batch prep (16)   [blocks 0..143]
//   P6: GEMM, persistent tile loop over 1024 tiles
// Grid = 2 * num_SMs (exactly 2 blocks/SM resident -> barrier is deadlock-free).

#define MPAD 68
#define GA 132
#define GZ 68

__device__ float g_AP[9][4096];      // A_bar^p, p=1..8
__device__ float g_A16[4096], g_A32[4096], g_A64[4096];
__device__ float g_CH[8][8192];      // CH[h] = C * A8^h (h=1..7)
__device__ float g_W[64][64];        // W[j] = A_bar^j B_bar
__device__ float g_ktab[64][128];    // k[j][c]
__device__ float g_G[64][8192];      // Ghat[jj][c*64+s]
__device__ float g_Z[128][1024];     // rows 0..63 u-chunks, 64..127 states
__device__ unsigned g_cnt = 0;
__device__ volatile unsigned g_gen = 0;

// ---------------- packed f32x2 helpers ----------------
#define PACK2(d, x) asm("mov.b64 %0, {%1, %1};" : "=l"(d) : "r"(__float_as_uint(x)))
#define FMA2(d, a, b) asm("fma.rn.f32x2 %0, %1, %2, %0;" : "+l"(d) : "l"(a), "l"(b))

__device__ __forceinline__ float f32x2_get(unsigned long long v, int hi) {
    return hi ? __uint_as_float((unsigned)(v >> 32)) : __uint_as_float((unsigned)v);
}

// ---------------- grid-wide barrier (all blocks resident) ----------------
__device__ __forceinline__ void gbar() {
    __syncthreads();
    if (threadIdx.x == 0) {
        unsigned nb = gridDim.x;
        __threadfence();
        unsigned gen = g_gen;
        unsigned old = atomicInc(&g_cnt, nb - 1);   // wraps to 0 at nb-1
        if (old == nb - 1) {
            __threadfence();
            g_gen = gen + 1;
        } else {
            while (g_gen == gen) __nanosleep(64);
            __threadfence();
        }
    }
    __syncthreads();
}

// ---------------- register-blocked 64x64 matmul core ----------------
__device__ __forceinline__ void mm64R(const float* __restrict__ xT,
                                      const float* __restrict__ ys,
                                      float* __restrict__ O, int tid) {
    int tr = tid & 15, tc = tid >> 4;
    float a00=0,a01=0,a02=0,a03=0, a10=0,a11=0,a12=0,a13=0;
    float a20=0,a21=0,a22=0,a23=0, a30=0,a31=0,a32=0,a33=0;
    #pragma unroll 4
    for (int s = 0; s < 64; s++) {
        float4 xv = *(const float4*)(xT + s * MPAD + tr * 4);
        float4 yv = *(const float4*)(ys + s * MPAD + tc * 4);
        a00 += xv.x*yv.x; a01 += xv.x*yv.y; a02 += xv.x*yv.z; a03 += xv.x*yv.w;
        a10 += xv.y*yv.x; a11 += xv.y*yv.y; a12 += xv.y*yv.z; a13 += xv.y*yv.w;
        a20 += xv.z*yv.x; a21 += xv.z*yv.y; a22 += xv.z*yv.z; a23 += xv.z*yv.w;
        a30 += xv.w*yv.x; a31 += xv.w*yv.y; a32 += xv.w*yv.z; a33 += xv.w*yv.w;
    }
    float4 o0 = {a00,a01,a02,a03}; *(float4*)(O + (tr*4+0)*64 + tc*4) = o0;
    float4 o1 = {a10,a11,a12,a13}; *(float4*)(O + (tr*4+1)*64 + tc*4) = o1;
    float4 o2 = {a20,a21,a22,a23}; *(float4*)(O + (tr*4+2)*64 + tc*4) = o2;
    float4 o3 = {a30,a31,a32,a33}; *(float4*)(O + (tr*4+3)*64 + tc*4) = o3;
}

__device__ __forceinline__ void loadT(const float* __restrict__ G, float* xT, int tid) {
    for (int idx = tid; idx < 4096; idx += 256) {
        int i = idx >> 6, s = idx & 63;
        xT[s * MPAD + i] = G[idx];
    }
}
__device__ __forceinline__ void loadN(const float* __restrict__ G, float* ys, int tid) {
    for (int idx = tid; idx < 4096; idx += 256)
        ys[(idx >> 6) * MPAD + (idx & 63)] = G[idx];
}
__device__ __forceinline__ void loadTrows(const float* __restrict__ G, int row0,
                                          float* xT, int tid) {
    for (int idx = tid; idx < 4096; idx += 256) {
        int i = idx >> 6, s = idx & 63;
        xT[s * MPAD + i] = G[(row0 + i) * 64 + s];
    }
}

// ---------------------------------------------------------------------------
__global__ __launch_bounds__(256, 2) void k_all(const float* __restrict__ A,
                                                const float* __restrict__ B,
                                                const float* __restrict__ C,
                                                const float* __restrict__ D,
                                                const float* __restrict__ dtp,
                                                const float* __restrict__ u,
                                                float* __restrict__ out) {
    extern __shared__ float sm[];
    __shared__ float aux[704];
    __shared__ float rdiag[64];
    int tid = threadIdx.x, bid = blockIdx.x;

    // ======== P0: discretization (block 0) ========
    if (bid == 0) {
        float* Ao = sm;                 // [64][65]
        float* Xs = sm + 64 * 65;       // [64][MPAD]  cols 0..63 A_bar, col 64 B_bar
        float* xT = Xs + 64 * MPAD;     // [64][MPAD]
        float dt = dtp[0], hd = 0.5f * dt;
        for (int idx = tid; idx < 4096; idx += 256)
            Ao[(idx >> 6) * 65 + (idx & 63)] = A[idx];
        __syncthreads();
        if (tid < 64) rdiag[tid] = 1.f / (1.f - hd * Ao[tid * 65 + tid]);
        __syncthreads();
        if (tid < 65) {
            int c = tid;
            for (int i = 0; i < 64; i++) {
                float acc0, acc1 = 0.f;
                if (c < 64) acc0 = ((i == c) ? 1.f : 0.f) + hd * Ao[i * 65 + c];
                else        acc0 = dt * B[i];
                int j = 0;
                for (; j + 1 < i; j += 2) {
                    acc0 += hd * Ao[i * 65 + j]     * Xs[j * MPAD + c];
                    acc1 += hd * Ao[i * 65 + j + 1] * Xs[(j + 1) * MPAD + c];
                }
                if (j < i) acc0 += hd * Ao[i * 65 + j] * Xs[j * MPAD + c];
                Xs[i * MPAD + c] = (acc0 + acc1) * rdiag[i];
            }
        }
        __syncthreads();
        for (int idx = tid; idx < 4096; idx += 256) {
            int i = idx >> 6, s = idx & 63;
            float v = Xs[i * MPAD + s];
            g_AP[1][idx] = v;
            xT[s * MPAD + i] = v;
        }
        if (tid < 64) g_W[0][tid] = Xs[tid * MPAD + 64];
        __syncthreads();
        mm64R(xT, Xs, g_AP[2], tid);
    }
    gbar();

    // ======== P1: A4, A8, w8 chain (block 0, serial) ========
    if (bid == 0) {
        float* s1 = sm;
        float* s2 = sm + 64 * MPAD;
        loadT(g_AP[2], s1, tid); loadN(g_AP[2], s2, tid);
        __syncthreads();
        mm64R(s1, s2, g_AP[4], tid);
        __syncthreads();
        loadT(g_AP[4], s1, tid); loadN(g_AP[4], s2, tid);
        __syncthreads();
        mm64R(s1, s2, g_AP[8], tid);
        __syncthreads();
        // w8 chain: w8[q] = A8 * w8[q-1] -> g_W[8q]
        loadN(g_AP[8], s2, tid);
        if (tid < 64) aux[tid] = g_W[0][tid];
        __syncthreads();
        int i = tid & 63, q4 = tid >> 6;
        for (int q = 1; q < 8; q++) {
            float acc = 0.f;
            #pragma unroll
            for (int s = q4 * 16; s < q4 * 16 + 16; s++)
                acc += s2[i * MPAD + s] * aux[s];
            aux[64 + q4 * 64 + i] = acc;
            __syncthreads();
            if (q4 == 0) {
                float v = aux[64 + i] + aux[128 + i] + aux[192 + i] + aux[256 + i];
                aux[i] = v;
                g_W[8 * q][i] = v;
            }
            __syncthreads();
        }
    }
    gbar();

    // ======== P2: A16 | CH1 | A3+A7 | A5 | A6 ========
    {
        float* s1 = sm;
        float* s2 = sm + 64 * MPAD;
        if (bid == 0) {
            loadT(g_AP[8], s1, tid); loadN(g_AP[8], s2, tid);
            __syncthreads();
            mm64R(s1, s2, g_A16, tid);
        } else if (bid <= 2) {
            loadTrows(C, (bid - 1) * 64, s1, tid); loadN(g_AP[8], s2, tid);
            __syncthreads();
            mm64R(s1, s2, g_CH[1] + (bid - 1) * 4096, tid);
        } else if (bid == 3) {
            loadT(g_AP[1], s1, tid); loadN(g_AP[2], s2, tid);
            __syncthreads();
            mm64R(s1, s2, g_AP[3], tid);
            __syncthreads();
            loadT(g_AP[3], s1, tid); loadN(g_AP[4], s2, tid);
            __syncthreads();
            mm64R(s1, s2, g_AP[7], tid);
        } else if (bid == 4) {
            loadT(g_AP[1], s1, tid); loadN(g_AP[4], s2, tid);
            __syncthreads();
            mm64R(s1, s2, g_AP[5], tid);
        } else if (bid == 5) {
            loadT(g_AP[2], s1, tid); loadN(g_AP[4], s2, tid);
            __syncthreads();
            mm64R(s1, s2, g_AP[6], tid);
        }
    }
    gbar();

    // ======== P3: A32 | CH2 | CH3 | W expansion ========
    {
        float* s1 = sm;
        float* s2 = sm + 64 * MPAD;
        if (bid == 0) {
            loadT(g_A16, s1, tid); loadN(g_A16, s2, tid);
            __syncthreads();
            mm64R(s1, s2, g_A32, tid);
        } else if (bid <= 2) {
            loadTrows(C, (bid - 1) * 64, s1, tid); loadN(g_A16, s2, tid);
            __syncthreads();
            mm64R(s1, s2, g_CH[2] + (bid - 1) * 4096, tid);
        } else if (bid <= 4) {
            loadTrows(g_CH[1], (bid - 3) * 64, s1, tid); loadN(g_A16, s2, tid);
            __syncthreads();
            mm64R(s1, s2, g_CH[3] + (bid - 3) * 4096, tid);
        } else if (bid <= 8) {
            int p = bid - 5;
            int r0 = 2 * p + 1, r1 = 2 * p + 2;
            loadN(g_AP[r0], s1, tid);
            if (r1 < 8) loadN(g_AP[r1], s2, tid);
            for (int idx = tid; idx < 512; idx += 256)
                aux[idx] = g_W[8 * (idx >> 6)][idx & 63];   // aux[q*64+s] = w8[q][s]
            __syncthreads();
            for (int idx = tid; idx < 512; idx += 256) {
                int q = idx >> 6, i = idx & 63;
                float a0 = 0.f, a1 = 0.f;
                #pragma unroll 8
                for (int s = 0; s < 64; s += 2) {
                    a0 += s1[i * MPAD + s]     * aux[q * 64 + s];
                    a1 += s1[i * MPAD + s + 1] * aux[q * 64 + s + 1];
                }
                g_W[8 * q + r0][i] = a0 + a1;
                if (r1 < 8) {
                    float b0 = 0.f, b1 = 0.f;
                    #pragma unroll 8
                    for (int s = 0; s < 64; s += 2) {
                        b0 += s2[i * MPAD + s]     * aux[q * 64 + s];
                        b1 += s2[i * MPAD + s + 1] * aux[q * 64 + s + 1];
                    }
                    g_W[8 * q + r1][i] = b0 + b1;
                }
            }
        }
    }
    gbar();

    // ======== P4: A64 | CH4..7 | ktab ========
    {
        if (bid == 0) {
            float* s1 = sm;
            float* s2 = sm + 64 * MPAD;
            loadT(g_A32, s1, tid); loadN(g_A32, s2, tid);
            __syncthreads();
            mm64R(s1, s2, g_A64, tid);
        } else if (bid <= 8) {
            float* s1 = sm;
            float* s2 = sm + 64 * MPAD;
            int p = bid - 1, which = p >> 1, half = p & 1;
            const float* srcs[4] = { C, g_CH[1], g_CH[2], g_CH[3] };
            loadTrows(srcs[which], half * 64, s1, tid);
            loadN(g_A32, s2, tid);
            __syncthreads();
            mm64R(s1, s2, g_CH[4 + which] + half * 4096, tid);
        } else if (bid <= 16) {
            // ktab[8hi+lo][c] = C[c] . W[8hi+lo]
            float* Cs = sm;                 // [128][65]
            float* ws = sm + 128 * 65;      // [8][64]
            int hi = bid - 9;
            for (int idx = tid; idx < 8192; idx += 256)
                Cs[(idx >> 6) * 65 + (idx & 63)] = C[idx];
            for (int idx = tid; idx < 512; idx += 256)
                ws[idx] = g_W[8 * hi + (idx >> 6)][idx & 63];
            __syncthreads();
            int c = tid >> 1, lo0 = (tid & 1) * 4;
            float a0 = 0, a1 = 0, a2 = 0, a3 = 0;
            #pragma unroll 4
            for (int s = 0; s < 64; s++) {
                float cv = Cs[c * 65 + s];
                a0 += cv * ws[(lo0 + 0) * 64 + s];
                a1 += cv * ws[(lo0 + 1) * 64 + s];
                a2 += cv * ws[(lo0 + 2) * 64 + s];
                a3 += cv * ws[(lo0 + 3) * 64 + s];
            }
            g_ktab[hi * 8 + lo0 + 0][c] = a0;
            g_ktab[hi * 8 + lo0 + 1][c] = a1;
            g_ktab[hi * 8 + lo0 + 2][c] = a2;
            g_ktab[hi * 8 + lo0 + 3][c] = a3;
        }
    }
    gbar();

    // ======== P5: Ghat (0..127) | prep (128..143) ========
    if (bid < 128) {
        float* xT = sm;
        float* ys = sm + 64 * MPAD;
        int jj = bid >> 1, ch0 = (bid & 1) << 6;
        int hi = jj >> 3, l = (jj & 7) + 1;
        const float* __restrict__ CHp = hi ? g_CH[hi] : C;
        loadTrows(CHp, ch0, xT, tid);
        loadN(g_AP[l], ys, tid);
        __syncthreads();
        mm64R(xT, ys, g_G[jj] + ch0 * 64, tid);
    } else if (bid < 144) {
        float* us  = sm;                  // [64][66]
        float* Fs  = sm + 64 * 66;        // [64][65]  Fs[i][s] = W[63-i][s]
        float* Sm  = Fs + 64 * 65;        // [64][65]
        float* ATs = Sm + 64 * 65;        // [64][65]  A_bar^64
        float* xv  = ATs + 64 * 65;       // [64]
        float* part = xv + 64;            // [4][64]
        int b = bid - 128;
        for (int idx = tid; idx < 4096; idx += 256) {
            int m = idx >> 6, j = idx & 63;
            us[m * 66 + j] = u[b * 4096 + idx];
        }
        for (int idx = tid; idx < 4096; idx += 256) {
            int i = idx >> 6, s = idx & 63;
            Fs[i * 65 + s]  = g_W[63 - i][s];
            ATs[i * 65 + s] = g_A64[idx];
        }
        __syncthreads();
        for (int idx = tid; idx < 4096; idx += 256) {
            int m = idx >> 6, s = idx & 63;
            float a0 = 0, a1 = 0;
            #pragma unroll 8
            for (int i = 0; i < 64; i += 2) {
                a0 += Fs[i * 65 + s]       * us[m * 66 + i];
                a1 += Fs[(i + 1) * 65 + s] * us[m * 66 + i + 1];
            }
            Sm[m * 65 + s] = a0 + a1;
        }
        for (int idx = tid; idx < 4096; idx += 256) {
            int j = idx >> 6, m = idx & 63;
            g_Z[j][b * 64 + m] = us[m * 66 + j];
        }
        if (tid < 64) xv[tid] = 0.f;
        __syncthreads();
        int s = tid & 63, q = tid >> 6;
        for (int m = 0; m < 64; m++) {
            if (q == 0) g_Z[64 + s][b * 64 + m] = xv[s];
            float acc = 0.f;
            #pragma unroll
            for (int s2 = q * 16; s2 < q * 16 + 16; s2++)
                acc += ATs[s * 65 + s2] * xv[s2];
            part[q * 64 + s] = acc;
            __syncthreads();
            if (q == 0)
                xv[s] = part[s] + part[64 + s] + part[128 + s] + part[192 + s]
                      + Sm[m * 65 + s];
            __syncthreads();
        }
    }
    gbar();

    // ======== P6: GEMM, persistent tile loop ========
    {
        float* As = sm;                   // [128][GA]
        float* Zs = sm + 128 * GA;        // [128][GZ]
        float* kt = Zs + 128 * GZ;        // [128]
        for (int t = bid; t < 1024; t += gridDim.x) {
            int n0 = (t & 15) * 64;
            int c0 = (t >> 4) * 2;

            if (tid < 128) kt[tid] = g_ktab[tid & 63][c0 + (tid >> 6)];
            for (int idx = tid; idx < 8192; idx += 256) {
                int k = idx >> 6, n = idx & 63;
                Zs[k * GZ + n] = g_Z[k][n0 + n];
            }
            for (int idx = tid; idx < 8192; idx += 256) {
                int s = idx & 63, jj = (idx >> 6) & 63, cc = idx >> 12;
                As[(64 + s) * GA + cc * 64 + jj] = g_G[jj][(c0 + cc) * 64 + s];
            }
            __syncthreads();
            for (int idx = tid; idx < 8192; idx += 256) {
                int jj = idx & 63, k = (idx >> 6) & 63, cc = idx >> 12;
                As[k * GA + cc * 64 + jj] = (k <= jj) ? kt[cc * 64 + (jj - k)] : 0.f;
            }
            __syncthreads();

            if (tid < 128) {
                int tr = tid & 15, tc = tid >> 4;      // tc 0..7
                const float* Ab = As + tr * 4;
                const float* Zb = Zs + tc * 8;

                unsigned long long acc[8][4];
                #pragma unroll
                for (int i = 0; i < 8; i++)
                    #pragma unroll
                    for (int j = 0; j < 4; j++) acc[i][j] = 0ull;

                #pragma unroll 2
                for (int k = 0; k < 128; k++) {
                    float4 a0 = *(const float4*)(Ab + k * GA);
                    float4 a1 = *(const float4*)(Ab + k * GA + 64);
                    ulonglong2 zl = *(const ulonglong2*)(Zb + k * GZ);
                    ulonglong2 zh = *(const ulonglong2*)(Zb + k * GZ + 4);
                    unsigned long long zp[4] = { zl.x, zl.y, zh.x, zh.y };
                    unsigned long long ap[8];
                    PACK2(ap[0], a0.x); PACK2(ap[1], a0.y);
                    PACK2(ap[2], a0.z); PACK2(ap[3], a0.w);
                    PACK2(ap[4], a1.x); PACK2(ap[5], a1.y);
                    PACK2(ap[6], a1.z); PACK2(ap[7], a1.w);
                    #pragma unroll
                    for (int ri = 0; ri < 8; ri++)
                        #pragma unroll
                        for (int cj = 0; cj < 4; cj++)
                            FMA2(acc[ri][cj], ap[ri], zp[cj]);
                }

                float Dv0 = D[c0], Dv1 = D[c0 + 1];
                int jb = tr * 4;
                #pragma unroll
                for (int j = 0; j < 8; j++) {
                    int n = tc * 8 + j, gn = n0 + n, b = gn >> 6, mm = gn & 63;
                    int cj = j >> 1, lh = j & 1;
                    float u0 = Zs[(jb + 0) * GZ + n];
                    float u1 = Zs[(jb + 1) * GZ + n];
                    float u2 = Zs[(jb + 2) * GZ + n];
                    float u3 = Zs[(jb + 3) * GZ + n];
                    float4 o0 = { f32x2_get(acc[0][cj], lh) + Dv0 * u0,
                                  f32x2_get(acc[1][cj], lh) + Dv0 * u1,
                                  f32x2_get(acc[2][cj], lh) + Dv0 * u2,
                                  f32x2_get(acc[3][cj], lh) + Dv0 * u3 };
                    *(float4*)&out[(b * 128 + c0) * 4096 + mm * 64 + jb] = o0;
                    float4 o1 = { f32x2_get(acc[4][cj], lh) + Dv1 * u0,
                                  f32x2_get(acc[5][cj], lh) + Dv1 * u1,
                                  f32x2_get(acc[6][cj], lh) + Dv1 * u2,
                                  f32x2_get(acc[7][cj], lh) + Dv1 * u3 };
                    *(float4*)&out[(b * 128 + c0 + 1) * 4096 + mm * 64 + jb] = o1;
                }
            }
            __syncthreads();
        }
    }
}

// ---------------------------------------------------------------------------
extern "C" void kernel_launch(void* const* d_in, const int* in_sizes, int n_in,
                              void* d_out, int out_size) {
    const float *u = 0, *A = 0, *B = 0, *C = 0, *D = 0, *dt = 0;
    for (int i = 0; i < n_in; i++) {
        const float* p = (const float*)d_in[i];
        switch (in_sizes[i]) {
            case 65536: u = p;  break;
            case 4096:  A = p;  break;
            case 64:    B = p;  break;
            case 8192:  C = p;  break;
            case 128:   D = p;  break;
            case 1:     dt = p; break;
        }
    }
    const int smem = (128 * GA + 128 * GZ + 128) * sizeof(float);   // 102912
    cudaFuncSetAttribute(k_all, cudaFuncAttributeMaxDynamicSharedMemorySize, smem);

    int dev = 0, sms = 148;
    cudaGetDevice(&dev);
    cudaDeviceGetAttribute(&sms, cudaDevAttrMultiProcessorCount, dev);
    int NB = 2 * sms;          // exactly 2 resident blocks per SM (smem-limited)
    if (NB < 152) NB = 152;    // phase P5 needs >= 144 blocks; safety floor

    k_all<<<NB, 256, smem>>>(A, B, C, D, dt, u, (float*)d_out);
}